// round 5
// baseline (speedup 1.0000x reference)
#include <cuda_runtime.h>
#include <cstdint>
#include <cstddef>

#define B_  32
#define P_  2048
#define D_  256
#define BP_ (B_ * P_)   // 65536

// ---------------- device scratch (static allocation: allowed) ----------------
__device__ float g_H[(size_t)BP_ * D_];        // 64 MB
__device__ float g_logits[(size_t)BP_ * P_];   // 512 MB
__device__ float g_agg[(size_t)BP_ * D_];      // 64 MB
__device__ float g_rowoff[BP_];                // m + log(sum exp)
__device__ float g_wc[BP_];                    // per-row gate scalar
__device__ float g_weff[D_];
__device__ float g_beff;

// ---------------- kernel: w_eff = cur_w @ gate_w, b_eff = cur_b.gate_w + gate_b
__global__ void k_weff(const float* __restrict__ cur_w, const float* __restrict__ cur_b,
                       const float* __restrict__ gate_w, const float* __restrict__ gate_b)
{
    __shared__ float gw[D_];
    __shared__ float red[D_];
    int k = threadIdx.x;
    gw[k] = gate_w[k];
    __syncthreads();
    float s = 0.f;
#pragma unroll 8
    for (int d = 0; d < D_; d++) s += cur_w[k * D_ + d] * gw[d];
    g_weff[k] = s;
    red[k] = cur_b[k] * gw[k];
    __syncthreads();
    for (int off = 128; off > 0; off >>= 1) {
        if (k < off) red[k] += red[k + off];
        __syncthreads();
    }
    if (k == 0) g_beff = red[0] + gate_b[0];
}

// ---------------- kernel: wc[row] = x[row,:].w_eff + b_eff  (1 warp / row)
__global__ void k_wc(const float* __restrict__ x)
{
    int row  = blockIdx.x * 8 + (threadIdx.x >> 5);
    int lane = threadIdx.x & 31;
    const float* xr = x + (size_t)row * D_;
    float s = 0.f;
#pragma unroll
    for (int i = 0; i < 8; i++) s += xr[lane + 32 * i] * g_weff[lane + 32 * i];
#pragma unroll
    for (int o = 16; o; o >>= 1) s += __shfl_xor_sync(0xffffffffu, s, o);
    if (lane == 0) g_wc[row] = s + g_beff;
}

// ---------------- generic SGEMM + bias: C[M,N] = A[M,K] @ B[K,N] + bias[N]
// block tile 128x64x16, 256 threads, 8x4 per thread. M,N,K assumed multiples.
__global__ __launch_bounds__(256) void k_gemm_bias(
    const float* __restrict__ A, const float* __restrict__ Bm,
    const float* __restrict__ bias, float* __restrict__ C,
    int N, int K)
{
    __shared__ float As[16][128];
    __shared__ float Bs[16][64];
    const int tid  = threadIdx.x;
    const int tx   = tid & 15;
    const int ty   = tid >> 4;
    const int row0 = blockIdx.y * 128;
    const int col0 = blockIdx.x * 64;

    const int a_r = tid >> 1;
    const int a_c = (tid & 1) * 8;
    const int b_r = tid >> 4;
    const int b_c = (tid & 15) * 4;

    const float* Ap = A  + (size_t)(row0 + a_r) * K + a_c;
    const float* Bp = Bm + (size_t)b_r * N + col0 + b_c;

    float acc[8][4];
#pragma unroll
    for (int i = 0; i < 8; i++)
#pragma unroll
        for (int j = 0; j < 4; j++) acc[i][j] = 0.f;

    for (int k0 = 0; k0 < K; k0 += 16) {
        float4 av0 = *(const float4*)(Ap + k0);
        float4 av1 = *(const float4*)(Ap + k0 + 4);
        float4 bv  = *(const float4*)(Bp + (size_t)k0 * N);
        As[a_c + 0][a_r] = av0.x; As[a_c + 1][a_r] = av0.y;
        As[a_c + 2][a_r] = av0.z; As[a_c + 3][a_r] = av0.w;
        As[a_c + 4][a_r] = av1.x; As[a_c + 5][a_r] = av1.y;
        As[a_c + 6][a_r] = av1.z; As[a_c + 7][a_r] = av1.w;
        *(float4*)&Bs[b_r][b_c] = bv;
        __syncthreads();
#pragma unroll
        for (int k = 0; k < 16; k++) {
            float4 a0 = *(const float4*)&As[k][ty * 8];
            float4 a1 = *(const float4*)&As[k][ty * 8 + 4];
            float4 b0 = *(const float4*)&Bs[k][tx * 4];
            float a[8] = {a0.x, a0.y, a0.z, a0.w, a1.x, a1.y, a1.z, a1.w};
            float b[4] = {b0.x, b0.y, b0.z, b0.w};
#pragma unroll
            for (int i = 0; i < 8; i++)
#pragma unroll
                for (int j = 0; j < 4; j++)
                    acc[i][j] += a[i] * b[j];
        }
        __syncthreads();
    }

    float4 bb = *(const float4*)(bias + col0 + tx * 4);
#pragma unroll
    for (int i = 0; i < 8; i++) {
        int r = row0 + ty * 8 + i;
        float4 v = make_float4(acc[i][0] + bb.x, acc[i][1] + bb.y,
                               acc[i][2] + bb.z, acc[i][3] + bb.w);
        *(float4*)(C + (size_t)r * N + col0 + tx * 4) = v;
    }
}

// ---------------- kernel: per-row softmax offset = max + log(sum exp) (1 warp / row)
__global__ void k_rowstat()
{
    int row  = blockIdx.x * 8 + (threadIdx.x >> 5);
    int lane = threadIdx.x & 31;
    const float4* L4 = (const float4*)(g_logits + (size_t)row * P_);
    float m = -1e30f;
#pragma unroll 4
    for (int i = lane; i < P_ / 4; i += 32) {
        float4 v = L4[i];
        m = fmaxf(m, fmaxf(fmaxf(v.x, v.y), fmaxf(v.z, v.w)));
    }
#pragma unroll
    for (int o = 16; o; o >>= 1) m = fmaxf(m, __shfl_xor_sync(0xffffffffu, m, o));
    float s = 0.f;
#pragma unroll 4
    for (int i = lane; i < P_ / 4; i += 32) {
        float4 v = L4[i];
        s += __expf(v.x - m) + __expf(v.y - m) + __expf(v.z - m) + __expf(v.w - m);
    }
#pragma unroll
    for (int o = 16; o; o >>= 1) s += __shfl_xor_sync(0xffffffffu, s, o);
    if (lane == 0) g_rowoff[row] = m + __logf(s);
}

// ---------------- kernel: agg[b,p,:] = sum_{q<=p} exp(logits[p,q]-off[p]) * x[b,q,:]
// block: 32 rows x 256 cols (full D), K loop truncated at p0+32 (triangular skip)
__global__ __launch_bounds__(256) void k_agg(const float* __restrict__ x)
{
    const int b  = blockIdx.z;
    const int p0 = blockIdx.x * 32;
    const int tid = threadIdx.x;
    const int tx  = tid & 31;
    const int ty  = tid >> 5;

    __shared__ float As[16][36];
    __shared__ float Bs[16][256];
    __shared__ float ro[32];

    if (tid < 32) ro[tid] = g_rowoff[b * P_ + p0 + tid];

    const int ar = tid >> 3;
    const int ac = (tid & 7) * 2;
    const float* Lp = g_logits + (size_t)(b * P_ + p0 + ar) * P_ + ac;
    const float* xb = x + (size_t)b * P_ * D_;

    float acc[4][8];
#pragma unroll
    for (int i = 0; i < 4; i++)
#pragma unroll
        for (int j = 0; j < 8; j++) acc[i][j] = 0.f;

    const int prow = p0 + ar;
    const int kend = p0 + 32;
    __syncthreads();
    const float off = ro[ar];

    for (int k0 = 0; k0 < kend; k0 += 16) {
        float2 l2 = *(const float2*)(Lp + k0);
        float v0 = (k0 + ac     <= prow) ? __expf(l2.x - off) : 0.f;
        float v1 = (k0 + ac + 1 <= prow) ? __expf(l2.y - off) : 0.f;
        float4 bv[4];
#pragma unroll
        for (int t = 0; t < 4; t++) {
            int idx4 = tid + t * 256;
            int br = idx4 >> 6;
            int bc = (idx4 & 63) * 4;
            bv[t] = *(const float4*)(xb + (size_t)(k0 + br) * D_ + bc);
        }
        As[ac][ar] = v0;
        As[ac + 1][ar] = v1;
#pragma unroll
        for (int t = 0; t < 4; t++) {
            int idx4 = tid + t * 256;
            int br = idx4 >> 6;
            int bc = (idx4 & 63) * 4;
            *(float4*)&Bs[br][bc] = bv[t];
        }
        __syncthreads();
#pragma unroll
        for (int k = 0; k < 16; k++) {
            float4 a  = *(const float4*)&As[k][ty * 4];
            float4 b0 = *(const float4*)&Bs[k][tx * 4];
            float4 b1 = *(const float4*)&Bs[k][tx * 4 + 128];
            float av[4] = {a.x, a.y, a.z, a.w};
            float bb[8] = {b0.x, b0.y, b0.z, b0.w, b1.x, b1.y, b1.z, b1.w};
#pragma unroll
            for (int i = 0; i < 4; i++)
#pragma unroll
                for (int j = 0; j < 8; j++)
                    acc[i][j] += av[i] * bb[j];
        }
        __syncthreads();
    }

#pragma unroll
    for (int i = 0; i < 4; i++) {
        size_t r = (size_t)(b * P_ + p0 + ty * 4 + i) * D_;
        float4 v0 = make_float4(acc[i][0], acc[i][1], acc[i][2], acc[i][3]);
        float4 v1 = make_float4(acc[i][4], acc[i][5], acc[i][6], acc[i][7]);
        *(float4*)(g_agg + r + tx * 4) = v0;
        *(float4*)(g_agg + r + tx * 4 + 128) = v1;
    }
}

// ---------------- kernel: out = LN(agg@mlp_w + mlp_b + wc*x) * ln_g + ln_b
// block: 32 rows x 256 cols (full D), K=256; warp owns whole rows -> LN via shfl
__global__ __launch_bounds__(256) void k_final(
    const float* __restrict__ x, const float* __restrict__ mlp_w,
    const float* __restrict__ mlp_b, const float* __restrict__ ln_g,
    const float* __restrict__ ln_b, float* __restrict__ out)
{
    const int row0 = blockIdx.x * 32;
    const int tid = threadIdx.x;
    const int tx  = tid & 31;
    const int ty  = tid >> 5;

    __shared__ float As[16][36];
    __shared__ float Bs[16][256];
    __shared__ float s_mb[256], s_g[256], s_b[256];

    s_mb[tid] = mlp_b[tid];
    s_g[tid]  = ln_g[tid];
    s_b[tid]  = ln_b[tid];

    const int ar = tid >> 3;
    const int ac = (tid & 7) * 2;
    const float* Ap = g_agg + (size_t)(row0 + ar) * D_ + ac;

    float acc[4][8];
#pragma unroll
    for (int i = 0; i < 4; i++)
#pragma unroll
        for (int j = 0; j < 8; j++) acc[i][j] = 0.f;

    __syncthreads();
    for (int k0 = 0; k0 < D_; k0 += 16) {
        float2 a2 = *(const float2*)(Ap + k0);
        float4 bv[4];
#pragma unroll
        for (int t = 0; t < 4; t++) {
            int idx4 = tid + t * 256;
            int br = idx4 >> 6;
            int bc = (idx4 & 63) * 4;
            bv[t] = *(const float4*)(mlp_w + (size_t)(k0 + br) * D_ + bc);
        }
        As[ac][ar] = a2.x;
        As[ac + 1][ar] = a2.y;
#pragma unroll
        for (int t = 0; t < 4; t++) {
            int idx4 = tid + t * 256;
            int br = idx4 >> 6;
            int bc = (idx4 & 63) * 4;
            *(float4*)&Bs[br][bc] = bv[t];
        }
        __syncthreads();
#pragma unroll
        for (int k = 0; k < 16; k++) {
            float4 a  = *(const float4*)&As[k][ty * 4];
            float4 b0 = *(const float4*)&Bs[k][tx * 4];
            float4 b1 = *(const float4*)&Bs[k][tx * 4 + 128];
            float av[4] = {a.x, a.y, a.z, a.w};
            float bb[8] = {b0.x, b0.y, b0.z, b0.w, b1.x, b1.y, b1.z, b1.w};
#pragma unroll
            for (int i = 0; i < 4; i++)
#pragma unroll
                for (int j = 0; j < 8; j++)
                    acc[i][j] += av[i] * bb[j];
        }
        __syncthreads();
    }

#pragma unroll
    for (int i = 0; i < 4; i++) {
        int r = row0 + ty * 4 + i;
        float w = g_wc[r];
        const float* xr = x + (size_t)r * D_;
        float4 x0 = *(const float4*)(xr + tx * 4);
        float4 x1 = *(const float4*)(xr + tx * 4 + 128);
        float xv[8] = {x0.x, x0.y, x0.z, x0.w, x1.x, x1.y, x1.z, x1.w};
        float h[8];
#pragma unroll
        for (int j = 0; j < 8; j++) {
            int c = (j < 4) ? (tx * 4 + j) : (tx * 4 + 128 + (j - 4));
            h[j] = acc[i][j] + s_mb[c] + w * xv[j];
        }
        float s = 0.f;
#pragma unroll
        for (int j = 0; j < 8; j++) s += h[j];
#pragma unroll
        for (int o = 16; o; o >>= 1) s += __shfl_xor_sync(0xffffffffu, s, o);
        float mu = s * (1.0f / 256.0f);
        float d = 0.f;
#pragma unroll
        for (int j = 0; j < 8; j++) { float t = h[j] - mu; d += t * t; }
#pragma unroll
        for (int o = 16; o; o >>= 1) d += __shfl_xor_sync(0xffffffffu, d, o);
        float inv = rsqrtf(d * (1.0f / 256.0f) + 1e-5f);

        float y[8];
#pragma unroll
        for (int j = 0; j < 8; j++) {
            int c = (j < 4) ? (tx * 4 + j) : (tx * 4 + 128 + (j - 4));
            y[j] = (h[j] - mu) * inv * s_g[c] + s_b[c];
        }
        float4 w0 = make_float4(y[0], y[1], y[2], y[3]);
        float4 w1 = make_float4(y[4], y[5], y[6], y[7]);
        *(float4*)(out + (size_t)r * D_ + tx * 4) = w0;
        *(float4*)(out + (size_t)r * D_ + tx * 4 + 128) = w1;
    }
}

// ---------------- launch ----------------
extern "C" void kernel_launch(void* const* d_in, const int* in_sizes, int n_in,
                              void* d_out, int out_size)
{
    const float* x      = (const float*)d_in[0];
    const float* mlp_w  = (const float*)d_in[1];
    const float* mlp_b  = (const float*)d_in[2];
    const float* his_w  = (const float*)d_in[3];
    const float* his_b  = (const float*)d_in[4];
    const float* cur_w  = (const float*)d_in[5];
    const float* cur_b  = (const float*)d_in[6];
    const float* wl_w   = (const float*)d_in[7];
    const float* wl_b   = (const float*)d_in[8];
    const float* gate_w = (const float*)d_in[9];
    const float* gate_b = (const float*)d_in[10];
    const float* ln_g   = (const float*)d_in[11];
    const float* ln_b   = (const float*)d_in[12];
    float* out = (float*)d_out;

    void* pH = nullptr;
    void* pL = nullptr;
    cudaGetSymbolAddress(&pH, g_H);
    cudaGetSymbolAddress(&pL, g_logits);
    float* gH = (float*)pH;
    float* gL = (float*)pL;

    // 1) fused gate weight precompute
    k_weff<<<1, 256>>>(cur_w, cur_b, gate_w, gate_b);
    // 2) per-row gate scalar wc
    k_wc<<<BP_ / 8, 256>>>(x);
    // 3) H = x @ his_w + his_b      (M=65536, N=256, K=256)
    k_gemm_bias<<<dim3(D_ / 64, BP_ / 128), 256>>>(x, his_w, his_b, gH, D_, D_);
    // 4) logits = H @ wl_w + wl_b   (M=65536, N=2048, K=256)
    k_gemm_bias<<<dim3(P_ / 64, BP_ / 128), 256>>>(gH, wl_w, wl_b, gL, P_, D_);
    // 5) per-row softmax offsets
    k_rowstat<<<BP_ / 8, 256>>>();
    // 6) agg = tril(softmax(logits)) @ x
    k_agg<<<dim3(P_ / 32, 1, B_), 256>>>(x);
    // 7) out = LN(agg @ mlp_w + mlp_b + wc*x)
    k_final<<<BP_ / 32, 256>>>(x, mlp_w, mlp_b, ln_g, ln_b, out);
    // 8) second output: origin (copy of x)
    cudaMemcpyAsync(out + (size_t)BP_ * D_, x,
                    (size_t)BP_ * D_ * sizeof(float),
                    cudaMemcpyDeviceToDevice);
}

// round 6
// speedup vs baseline: 1.3861x; 1.3861x over previous
#include <cuda_runtime.h>
#include <cstdint>
#include <cstddef>

#define B_  32
#define P_  2048
#define D_  256
#define BP_ (B_ * P_)   // 65536

// ---------------- device scratch ----------------
__device__ float g_H[(size_t)BP_ * D_];        // 64 MB
__device__ float g_logits[(size_t)BP_ * P_];   // 512 MB
__device__ float g_agg[(size_t)BP_ * D_];      // 64 MB
__device__ float g_rowoff[BP_];                // m + log(sum exp)
__device__ float g_wc[BP_];                    // per-row gate scalar
__device__ float g_weff[D_];
__device__ float g_beff;

// ---------------- helpers ----------------
__device__ __forceinline__ uint32_t f2tf32(float f) {
    uint32_t u;
    asm("cvt.rna.tf32.f32 %0, %1;" : "=r"(u) : "f"(f));
    return u;
}

__device__ __forceinline__ void mma_tf32(float4& c, const uint32_t a[4], const uint32_t b[2]) {
    asm volatile(
        "mma.sync.aligned.m16n8k8.row.col.f32.tf32.tf32.f32 "
        "{%0,%1,%2,%3}, {%4,%5,%6,%7}, {%8,%9}, {%0,%1,%2,%3};\n"
        : "+f"(c.x), "+f"(c.y), "+f"(c.z), "+f"(c.w)
        : "r"(a[0]), "r"(a[1]), "r"(a[2]), "r"(a[3]),
          "r"(b[0]), "r"(b[1]));
}

// ---------------- kernel: w_eff = cur_w @ gate_w, b_eff = cur_b.gate_w + gate_b
__global__ void k_weff(const float* __restrict__ cur_w, const float* __restrict__ cur_b,
                       const float* __restrict__ gate_w, const float* __restrict__ gate_b)
{
    __shared__ float gw[D_];
    __shared__ float red[D_];
    int k = threadIdx.x;
    gw[k] = gate_w[k];
    __syncthreads();
    float s = 0.f;
#pragma unroll 8
    for (int d = 0; d < D_; d++) s += cur_w[k * D_ + d] * gw[d];
    g_weff[k] = s;
    red[k] = cur_b[k] * gw[k];
    __syncthreads();
    for (int off = 128; off > 0; off >>= 1) {
        if (k < off) red[k] += red[k + off];
        __syncthreads();
    }
    if (k == 0) g_beff = red[0] + gate_b[0];
}

// ---------------- kernel: wc[row] = x[row,:].w_eff + b_eff  (1 warp / row)
__global__ void k_wc(const float* __restrict__ x)
{
    int row  = blockIdx.x * 8 + (threadIdx.x >> 5);
    int lane = threadIdx.x & 31;
    const float* xr = x + (size_t)row * D_;
    float s = 0.f;
#pragma unroll
    for (int i = 0; i < 8; i++) s += xr[lane + 32 * i] * g_weff[lane + 32 * i];
#pragma unroll
    for (int o = 16; o; o >>= 1) s += __shfl_xor_sync(0xffffffffu, s, o);
    if (lane == 0) g_wc[row] = s + g_beff;
}

// ---------------- TF32 tensor-core GEMM + bias: C[M,N] = A[M,K]@B[K,N] + bias[N]
// block tile 128x64, 8 warps, warp tile 32x32, K-step 32.
__global__ __launch_bounds__(256) void k_gemm_tf32(
    const float* __restrict__ A, const float* __restrict__ Bm,
    const float* __restrict__ bias, float* __restrict__ C,
    int N, int K)
{
    __shared__ uint32_t As[32][132];   // [k][m]
    __shared__ uint32_t Bs[32][68];    // [k][n]

    const int tid  = threadIdx.x;
    const int lane = tid & 31;
    const int warp = tid >> 5;
    const int wm = (warp & 3) * 32;
    const int wn = (warp >> 2) * 32;
    const int g   = lane >> 2;
    const int tig = lane & 3;
    const int row0 = blockIdx.y * 128;
    const int col0 = blockIdx.x * 64;

    // A loader: thread covers (m = tid&127, k in [(tid>>7)*16, +16))
    const int am = tid & 127;
    const int aq = (tid >> 7) * 16;
    const float* Ap = A + (size_t)(row0 + am) * K + aq;
    // B loader: thread covers (k = tid>>4 (+16), n4 = (tid&15)*4)
    const int brr = tid >> 4;
    const int bcc = (tid & 15) * 4;
    const float* Bp = Bm + (size_t)brr * N + col0 + bcc;

    float4 acc[2][4];
#pragma unroll
    for (int mi = 0; mi < 2; mi++)
#pragma unroll
        for (int ni = 0; ni < 4; ni++) acc[mi][ni] = make_float4(0.f, 0.f, 0.f, 0.f);

    for (int k0 = 0; k0 < K; k0 += 32) {
#pragma unroll
        for (int v = 0; v < 4; v++) {
            float4 a = *(const float4*)(Ap + k0 + v * 4);
            int kk = aq + v * 4;
            As[kk + 0][am] = f2tf32(a.x);
            As[kk + 1][am] = f2tf32(a.y);
            As[kk + 2][am] = f2tf32(a.z);
            As[kk + 3][am] = f2tf32(a.w);
        }
#pragma unroll
        for (int v = 0; v < 2; v++) {
            float4 b = *(const float4*)(Bp + (size_t)(k0 + v * 16) * N);
            uint32_t* dst = &Bs[brr + v * 16][bcc];
            dst[0] = f2tf32(b.x); dst[1] = f2tf32(b.y);
            dst[2] = f2tf32(b.z); dst[3] = f2tf32(b.w);
        }
        __syncthreads();
#pragma unroll
        for (int ks = 0; ks < 4; ks++) {
            const int kb = ks * 8;
            uint32_t af[2][4], bf[4][2];
#pragma unroll
            for (int mi = 0; mi < 2; mi++) {
                int rb = wm + mi * 16;
                af[mi][0] = As[kb + tig][rb + g];
                af[mi][1] = As[kb + tig][rb + g + 8];
                af[mi][2] = As[kb + tig + 4][rb + g];
                af[mi][3] = As[kb + tig + 4][rb + g + 8];
            }
#pragma unroll
            for (int ni = 0; ni < 4; ni++) {
                int cb = wn + ni * 8;
                bf[ni][0] = Bs[kb + tig][cb + g];
                bf[ni][1] = Bs[kb + tig + 4][cb + g];
            }
#pragma unroll
            for (int mi = 0; mi < 2; mi++)
#pragma unroll
                for (int ni = 0; ni < 4; ni++)
                    mma_tf32(acc[mi][ni], af[mi], bf[ni]);
        }
        __syncthreads();
    }

    // epilogue: +bias, store
#pragma unroll
    for (int mi = 0; mi < 2; mi++) {
        int r = row0 + wm + mi * 16 + g;
#pragma unroll
        for (int ni = 0; ni < 4; ni++) {
            int c = col0 + wn + ni * 8 + tig * 2;
            float b0 = bias[c], b1 = bias[c + 1];
            float2 v0 = make_float2(acc[mi][ni].x + b0, acc[mi][ni].y + b1);
            float2 v1 = make_float2(acc[mi][ni].z + b0, acc[mi][ni].w + b1);
            *(float2*)(C + (size_t)r * N + c) = v0;
            *(float2*)(C + (size_t)(r + 8) * N + c) = v1;
        }
    }
}

// ---------------- per-row softmax offset = max + log(sum exp)  (1 warp / row)
__global__ void k_rowstat()
{
    int row  = blockIdx.x * 8 + (threadIdx.x >> 5);
    int lane = threadIdx.x & 31;
    const float4* L4 = (const float4*)(g_logits + (size_t)row * P_);
    float m = -1e30f;
#pragma unroll 4
    for (int i = lane; i < P_ / 4; i += 32) {
        float4 v = L4[i];
        m = fmaxf(m, fmaxf(fmaxf(v.x, v.y), fmaxf(v.z, v.w)));
    }
#pragma unroll
    for (int o = 16; o; o >>= 1) m = fmaxf(m, __shfl_xor_sync(0xffffffffu, m, o));
    float s = 0.f;
#pragma unroll 4
    for (int i = lane; i < P_ / 4; i += 32) {
        float4 v = L4[i];
        s += __expf(v.x - m) + __expf(v.y - m) + __expf(v.z - m) + __expf(v.w - m);
    }
#pragma unroll
    for (int o = 16; o; o >>= 1) s += __shfl_xor_sync(0xffffffffu, s, o);
    if (lane == 0) g_rowoff[row] = m + __logf(s);
}

// ---------------- TF32 agg: agg[b,p,:] = sum_{q<=p} exp(logits[p,q]-off[p]) * x[b,q,:]
// block tile 32x256, 8 warps (each 32x32), K truncated at p0+32.
__global__ __launch_bounds__(256) void k_agg_tf32(const float* __restrict__ x)
{
    __shared__ uint32_t As[32][36];    // [k][m], exp weights
    __shared__ uint32_t Bs[32][260];   // [k][n], x tile

    const int b  = blockIdx.z;
    const int p0 = blockIdx.x * 32;
    const int tid  = threadIdx.x;
    const int lane = tid & 31;
    const int warp = tid >> 5;
    const int wn = warp * 32;
    const int g   = lane >> 2;
    const int tig = lane & 3;

    // A loader: thread (m = tid>>3, k4 = (tid&7)*4)
    const int ar  = tid >> 3;
    const int ac4 = (tid & 7) * 4;
    const int prow = p0 + ar;
    const float off = g_rowoff[b * P_ + prow];
    const float* Lp = g_logits + (size_t)(b * P_ + prow) * P_ + ac4;

    // B loader: thread (n4 = (tid&63)*4, k rows tid>>6 + v*4)
    const int bn4 = (tid & 63) * 4;
    const int br0 = tid >> 6;
    const float* xb = x + (size_t)b * P_ * D_;

    float4 acc[2][4];
#pragma unroll
    for (int mi = 0; mi < 2; mi++)
#pragma unroll
        for (int ni = 0; ni < 4; ni++) acc[mi][ni] = make_float4(0.f, 0.f, 0.f, 0.f);

    const int kend = p0 + 32;
    for (int k0 = 0; k0 < kend; k0 += 32) {
        {
            float4 l = *(const float4*)(Lp + k0);
            int kq = k0 + ac4;
            float e0 = (kq     <= prow) ? __expf(l.x - off) : 0.f;
            float e1 = (kq + 1 <= prow) ? __expf(l.y - off) : 0.f;
            float e2 = (kq + 2 <= prow) ? __expf(l.z - off) : 0.f;
            float e3 = (kq + 3 <= prow) ? __expf(l.w - off) : 0.f;
            As[ac4 + 0][ar] = f2tf32(e0);
            As[ac4 + 1][ar] = f2tf32(e1);
            As[ac4 + 2][ar] = f2tf32(e2);
            As[ac4 + 3][ar] = f2tf32(e3);
        }
#pragma unroll
        for (int v = 0; v < 8; v++) {
            int r = br0 + v * 4;
            float4 xv = *(const float4*)(xb + (size_t)(k0 + r) * D_ + bn4);
            uint32_t* dst = &Bs[r][bn4];
            dst[0] = f2tf32(xv.x); dst[1] = f2tf32(xv.y);
            dst[2] = f2tf32(xv.z); dst[3] = f2tf32(xv.w);
        }
        __syncthreads();
#pragma unroll
        for (int ks = 0; ks < 4; ks++) {
            const int kb = ks * 8;
            uint32_t af[2][4], bf[4][2];
#pragma unroll
            for (int mi = 0; mi < 2; mi++) {
                int rb = mi * 16;
                af[mi][0] = As[kb + tig][rb + g];
                af[mi][1] = As[kb + tig][rb + g + 8];
                af[mi][2] = As[kb + tig + 4][rb + g];
                af[mi][3] = As[kb + tig + 4][rb + g + 8];
            }
#pragma unroll
            for (int ni = 0; ni < 4; ni++) {
                int cb = wn + ni * 8;
                bf[ni][0] = Bs[kb + tig][cb + g];
                bf[ni][1] = Bs[kb + tig + 4][cb + g];
            }
#pragma unroll
            for (int mi = 0; mi < 2; mi++)
#pragma unroll
                for (int ni = 0; ni < 4; ni++)
                    mma_tf32(acc[mi][ni], af[mi], bf[ni]);
        }
        __syncthreads();
    }

#pragma unroll
    for (int mi = 0; mi < 2; mi++) {
        int r = p0 + mi * 16 + g;
#pragma unroll
        for (int ni = 0; ni < 4; ni++) {
            int c = wn + ni * 8 + tig * 2;
            float2 v0 = make_float2(acc[mi][ni].x, acc[mi][ni].y);
            float2 v1 = make_float2(acc[mi][ni].z, acc[mi][ni].w);
            *(float2*)(g_agg + (size_t)(b * P_ + r) * D_ + c) = v0;
            *(float2*)(g_agg + (size_t)(b * P_ + r + 8) * D_ + c) = v1;
        }
    }
}

// ---------------- kernel: out = LN(agg@mlp_w + mlp_b + wc*x) * ln_g + ln_b
__global__ __launch_bounds__(256) void k_final(
    const float* __restrict__ x, const float* __restrict__ mlp_w,
    const float* __restrict__ mlp_b, const float* __restrict__ ln_g,
    const float* __restrict__ ln_b, float* __restrict__ out)
{
    const int row0 = blockIdx.x * 32;
    const int tid = threadIdx.x;
    const int tx  = tid & 31;
    const int ty  = tid >> 5;

    __shared__ float As[16][36];
    __shared__ float Bs[16][256];
    __shared__ float s_mb[256], s_g[256], s_b[256];

    s_mb[tid] = mlp_b[tid];
    s_g[tid]  = ln_g[tid];
    s_b[tid]  = ln_b[tid];

    const int ar = tid >> 3;
    const int ac = (tid & 7) * 2;
    const float* Ap = g_agg + (size_t)(row0 + ar) * D_ + ac;

    float acc[4][8];
#pragma unroll
    for (int i = 0; i < 4; i++)
#pragma unroll
        for (int j = 0; j < 8; j++) acc[i][j] = 0.f;

    __syncthreads();
    for (int k0 = 0; k0 < D_; k0 += 16) {
        float2 a2 = *(const float2*)(Ap + k0);
        float4 bv[4];
#pragma unroll
        for (int t = 0; t < 4; t++) {
            int idx4 = tid + t * 256;
            int br = idx4 >> 6;
            int bc = (idx4 & 63) * 4;
            bv[t] = *(const float4*)(mlp_w + (size_t)(k0 + br) * D_ + bc);
        }
        As[ac][ar] = a2.x;
        As[ac + 1][ar] = a2.y;
#pragma unroll
        for (int t = 0; t < 4; t++) {
            int idx4 = tid + t * 256;
            int br = idx4 >> 6;
            int bc = (idx4 & 63) * 4;
            *(float4*)&Bs[br][bc] = bv[t];
        }
        __syncthreads();
#pragma unroll
        for (int k = 0; k < 16; k++) {
            float4 a  = *(const float4*)&As[k][ty * 4];
            float4 b0 = *(const float4*)&Bs[k][tx * 4];
            float4 b1 = *(const float4*)&Bs[k][tx * 4 + 128];
            float av[4] = {a.x, a.y, a.z, a.w};
            float bb[8] = {b0.x, b0.y, b0.z, b0.w, b1.x, b1.y, b1.z, b1.w};
#pragma unroll
            for (int i = 0; i < 4; i++)
#pragma unroll
                for (int j = 0; j < 8; j++)
                    acc[i][j] += av[i] * bb[j];
        }
        __syncthreads();
    }

#pragma unroll
    for (int i = 0; i < 4; i++) {
        int r = row0 + ty * 4 + i;
        float w = g_wc[r];
        const float* xr = x + (size_t)r * D_;
        float4 x0 = *(const float4*)(xr + tx * 4);
        float4 x1 = *(const float4*)(xr + tx * 4 + 128);
        float xv[8] = {x0.x, x0.y, x0.z, x0.w, x1.x, x1.y, x1.z, x1.w};
        float h[8];
#pragma unroll
        for (int j = 0; j < 8; j++) {
            int c = (j < 4) ? (tx * 4 + j) : (tx * 4 + 128 + (j - 4));
            h[j] = acc[i][j] + s_mb[c] + w * xv[j];
        }
        float s = 0.f;
#pragma unroll
        for (int j = 0; j < 8; j++) s += h[j];
#pragma unroll
        for (int o = 16; o; o >>= 1) s += __shfl_xor_sync(0xffffffffu, s, o);
        float mu = s * (1.0f / 256.0f);
        float d = 0.f;
#pragma unroll
        for (int j = 0; j < 8; j++) { float t = h[j] - mu; d += t * t; }
#pragma unroll
        for (int o = 16; o; o >>= 1) d += __shfl_xor_sync(0xffffffffu, d, o);
        float inv = rsqrtf(d * (1.0f / 256.0f) + 1e-5f);

        float y[8];
#pragma unroll
        for (int j = 0; j < 8; j++) {
            int c = (j < 4) ? (tx * 4 + j) : (tx * 4 + 128 + (j - 4));
            y[j] = (h[j] - mu) * inv * s_g[c] + s_b[c];
        }
        float4 w0 = make_float4(y[0], y[1], y[2], y[3]);
        float4 w1 = make_float4(y[4], y[5], y[6], y[7]);
        *(float4*)(out + (size_t)r * D_ + tx * 4) = w0;
        *(float4*)(out + (size_t)r * D_ + tx * 4 + 128) = w1;
    }
}

// ---------------- launch ----------------
extern "C" void kernel_launch(void* const* d_in, const int* in_sizes, int n_in,
                              void* d_out, int out_size)
{
    const float* x      = (const float*)d_in[0];
    const float* mlp_w  = (const float*)d_in[1];
    const float* mlp_b  = (const float*)d_in[2];
    const float* his_w  = (const float*)d_in[3];
    const float* his_b  = (const float*)d_in[4];
    const float* cur_w  = (const float*)d_in[5];
    const float* cur_b  = (const float*)d_in[6];
    const float* wl_w   = (const float*)d_in[7];
    const float* wl_b   = (const float*)d_in[8];
    const float* gate_w = (const float*)d_in[9];
    const float* gate_b = (const float*)d_in[10];
    const float* ln_g   = (const float*)d_in[11];
    const float* ln_b   = (const float*)d_in[12];
    float* out = (float*)d_out;

    void* pH = nullptr;
    void* pL = nullptr;
    cudaGetSymbolAddress(&pH, g_H);
    cudaGetSymbolAddress(&pL, g_logits);
    float* gH = (float*)pH;
    float* gL = (float*)pL;

    // 1) fused gate weight precompute
    k_weff<<<1, 256>>>(cur_w, cur_b, gate_w, gate_b);
    // 2) per-row gate scalar wc
    k_wc<<<BP_ / 8, 256>>>(x);
    // 3) H = x @ his_w + his_b   (tensor-core tf32)
    k_gemm_tf32<<<dim3(D_ / 64, BP_ / 128), 256>>>(x, his_w, his_b, gH, D_, D_);
    // 4) logits = H @ wl_w + wl_b (tensor-core tf32)
    k_gemm_tf32<<<dim3(P_ / 64, BP_ / 128), 256>>>(gH, wl_w, wl_b, gL, P_, D_);
    // 5) per-row softmax offsets
    k_rowstat<<<BP_ / 8, 256>>>();
    // 6) agg = tril(softmax(logits)) @ x  (tensor-core tf32, triangular skip)
    k_agg_tf32<<<dim3(P_ / 32, 1, B_), 256>>>(x);
    // 7) out = LN(agg @ mlp_w + mlp_b + wc*x)
    k_final<<<BP_ / 32, 256>>>(x, mlp_w, mlp_b, ln_g, ln_b, out);
    // 8) second output: origin (copy of x)
    cudaMemcpyAsync(out + (size_t)BP_ * D_, x,
                    (size_t)BP_ * D_ * sizeof(float),
                    cudaMemcpyDeviceToDevice);
}

// round 7
// speedup vs baseline: 2.1372x; 1.5419x over previous
#include <cuda_runtime.h>
#include <cstdint>
#include <cstddef>

#define B_  32
#define P_  2048
#define D_  256
#define BP_ (B_ * P_)   // 65536

// ---------------- device scratch ----------------
__device__ float g_H[(size_t)BP_ * D_];        // 64 MB
__device__ float g_logits[(size_t)BP_ * P_];   // 512 MB
__device__ float g_agg[(size_t)BP_ * D_];      // 64 MB
__device__ float g_rowoff[BP_];                // m + log(sum exp)
__device__ float g_wc[BP_];                    // per-row gate scalar
__device__ float g_weff[D_];
__device__ float g_beff;

// ---------------- helpers ----------------
__device__ __forceinline__ void mma_tf32(float4& c, const uint32_t a[4], const uint32_t b[2]) {
    asm volatile(
        "mma.sync.aligned.m16n8k8.row.col.f32.tf32.tf32.f32 "
        "{%0,%1,%2,%3}, {%4,%5,%6,%7}, {%8,%9}, {%0,%1,%2,%3};\n"
        : "+f"(c.x), "+f"(c.y), "+f"(c.z), "+f"(c.w)
        : "r"(a[0]), "r"(a[1]), "r"(a[2]), "r"(a[3]),
          "r"(b[0]), "r"(b[1]));
}

__device__ __forceinline__ void ldsm_x4(uint32_t r[4], uint32_t addr) {
    asm volatile("ldmatrix.sync.aligned.m8n8.x4.shared.b16 {%0,%1,%2,%3}, [%4];"
                 : "=r"(r[0]), "=r"(r[1]), "=r"(r[2]), "=r"(r[3]) : "r"(addr));
}

__device__ __forceinline__ void cp16(uint32_t dst_smem, const void* src) {
    asm volatile("cp.async.cg.shared.global [%0], [%1], 16;\n"
                 :: "r"(dst_smem), "l"(src));
}
#define CP_COMMIT()  asm volatile("cp.async.commit_group;\n" ::: "memory")
#define CP_WAIT(n)   asm volatile("cp.async.wait_group %0;\n" :: "n"(n) : "memory")

// ---------------- kernel: w_eff = cur_w @ gate_w, b_eff = cur_b.gate_w + gate_b
__global__ void k_weff(const float* __restrict__ cur_w, const float* __restrict__ cur_b,
                       const float* __restrict__ gate_w, const float* __restrict__ gate_b)
{
    __shared__ float gw[D_];
    __shared__ float red[D_];
    int k = threadIdx.x;
    gw[k] = gate_w[k];
    __syncthreads();
    float s = 0.f;
#pragma unroll 8
    for (int d = 0; d < D_; d++) s += cur_w[k * D_ + d] * gw[d];
    g_weff[k] = s;
    red[k] = cur_b[k] * gw[k];
    __syncthreads();
    for (int off = 128; off > 0; off >>= 1) {
        if (k < off) red[k] += red[k + off];
        __syncthreads();
    }
    if (k == 0) g_beff = red[0] + gate_b[0];
}

// ---------------- kernel: wc[row] = x[row,:].w_eff + b_eff  (1 warp / row)
__global__ void k_wc(const float* __restrict__ x)
{
    int row  = blockIdx.x * 8 + (threadIdx.x >> 5);
    int lane = threadIdx.x & 31;
    const float* xr = x + (size_t)row * D_;
    float s = 0.f;
#pragma unroll
    for (int i = 0; i < 8; i++) s += xr[lane + 32 * i] * g_weff[lane + 32 * i];
#pragma unroll
    for (int o = 16; o; o >>= 1) s += __shfl_xor_sync(0xffffffffu, s, o);
    if (lane == 0) g_wc[row] = s + g_beff;
}

// ---------------- TF32 GEMM v2: C[M,N] = A[M,K]@B[K,N] + bias[N]
// block 128x128, 8 warps (2m x 4n), warp tile 64x32, K-step 32.
// A smem [m][k] stride 36 (ldmatrix.x4 frags); B smem [k][n] stride 136 (pad-8, LDS.32).
// Double-buffered cp.async mainloop. Raw fp32 fed to tf32 MMA.
#define G_AS 36
#define G_BS 136
#define G_AW (128 * G_AS)            // 4608 words
#define G_BW (32 * G_BS)             // 4352 words
#define G_STG (G_AW + G_BW)          // 8960 words per stage

__global__ __launch_bounds__(256) void k_gemm_tf32(
    const float* __restrict__ A, const float* __restrict__ Bm,
    const float* __restrict__ bias, float* __restrict__ C,
    int N, int K)
{
    extern __shared__ float sm[];
    const uint32_t smb = (uint32_t)__cvta_generic_to_shared(sm);
    const uint32_t* smu = (const uint32_t*)sm;

    const int tid  = threadIdx.x;
    const int lane = tid & 31;
    const int warp = tid >> 5;
    const int wm = (warp & 1) * 64;
    const int wn = (warp >> 1) * 32;
    const int g   = lane >> 2;
    const int tig = lane & 3;
    const int row0 = blockIdx.y * 128;
    const int col0 = blockIdx.x * 128;

    // loaders
    const int am = tid & 127;
    const int aq = (tid >> 7) * 16;
    const float* Ap = A + (size_t)(row0 + am) * K + aq;
    const int bk  = tid >> 5;           // 0..7
    const int bn4 = (tid & 31) * 4;
    const float* Bp = Bm + (size_t)bk * N + col0 + bn4;

    // ldmatrix lane pointer components
    const int rowit = (lane & 7) + ((lane & 8) ? 8 : 0);
    const int colw  = (lane & 16) ? 4 : 0;

    float4 acc[4][4];
#pragma unroll
    for (int mi = 0; mi < 4; mi++)
#pragma unroll
        for (int ni = 0; ni < 4; ni++) acc[mi][ni] = make_float4(0.f, 0.f, 0.f, 0.f);

    const int nk = K / 32;

    // stage 0 loads
    {
        uint32_t base = smb;
#pragma unroll
        for (int v = 0; v < 4; v++)
            cp16(base + (uint32_t)(am * G_AS + aq + v * 4) * 4, Ap + v * 4);
#pragma unroll
        for (int v = 0; v < 4; v++)
            cp16(base + (uint32_t)(G_AW + (bk + v * 8) * G_BS + bn4) * 4,
                 Bp + (size_t)(v * 8) * N);
        CP_COMMIT();
    }

    for (int kt = 0; kt < nk; kt++) {
        const int s = kt & 1;
        if (kt + 1 < nk) {
            uint32_t base = smb + (uint32_t)((s ^ 1) * G_STG) * 4;
            const int k0 = (kt + 1) * 32;
#pragma unroll
            for (int v = 0; v < 4; v++)
                cp16(base + (uint32_t)(am * G_AS + aq + v * 4) * 4, Ap + k0 + v * 4);
#pragma unroll
            for (int v = 0; v < 4; v++)
                cp16(base + (uint32_t)(G_AW + (bk + v * 8) * G_BS + bn4) * 4,
                     Bp + (size_t)(k0 + v * 8) * N);
            CP_COMMIT();
            CP_WAIT(1);
        } else {
            CP_WAIT(0);
        }
        __syncthreads();

        const uint32_t aBase = smb + (uint32_t)(s * G_STG + (wm + rowit) * G_AS + colw) * 4;
        const int bBase = s * G_STG + G_AW;
#pragma unroll
        for (int ks = 0; ks < 4; ks++) {
            uint32_t af[4][4];
#pragma unroll
            for (int mi = 0; mi < 4; mi++)
                ldsm_x4(af[mi], aBase + (uint32_t)(mi * 16 * G_AS * 4 + ks * 32));
            uint32_t bf[4][2];
#pragma unroll
            for (int ni = 0; ni < 4; ni++) {
                int c = wn + ni * 8 + g;
                bf[ni][0] = smu[bBase + (ks * 8 + tig) * G_BS + c];
                bf[ni][1] = smu[bBase + (ks * 8 + tig + 4) * G_BS + c];
            }
#pragma unroll
            for (int mi = 0; mi < 4; mi++)
#pragma unroll
                for (int ni = 0; ni < 4; ni++)
                    mma_tf32(acc[mi][ni], af[mi], bf[ni]);
        }
        __syncthreads();
    }

    // epilogue: +bias, store
#pragma unroll
    for (int mi = 0; mi < 4; mi++) {
        int r = row0 + wm + mi * 16 + g;
#pragma unroll
        for (int ni = 0; ni < 4; ni++) {
            int c = col0 + wn + ni * 8 + tig * 2;
            float b0 = bias[c], b1 = bias[c + 1];
            float2 v0 = make_float2(acc[mi][ni].x + b0, acc[mi][ni].y + b1);
            float2 v1 = make_float2(acc[mi][ni].z + b0, acc[mi][ni].w + b1);
            *(float2*)(C + (size_t)r * N + c) = v0;
            *(float2*)(C + (size_t)(r + 8) * N + c) = v1;
        }
    }
}

// ---------------- per-row softmax offset = max + log(sum exp)  (1 warp / row)
__global__ void k_rowstat()
{
    int row  = blockIdx.x * 8 + (threadIdx.x >> 5);
    int lane = threadIdx.x & 31;
    const float4* L4 = (const float4*)(g_logits + (size_t)row * P_);
    float m = -1e30f;
#pragma unroll 4
    for (int i = lane; i < P_ / 4; i += 32) {
        float4 v = L4[i];
        m = fmaxf(m, fmaxf(fmaxf(v.x, v.y), fmaxf(v.z, v.w)));
    }
#pragma unroll
    for (int o = 16; o; o >>= 1) m = fmaxf(m, __shfl_xor_sync(0xffffffffu, m, o));
    float s = 0.f;
#pragma unroll 4
    for (int i = lane; i < P_ / 4; i += 32) {
        float4 v = L4[i];
        s += __expf(v.x - m) + __expf(v.y - m) + __expf(v.z - m) + __expf(v.w - m);
    }
#pragma unroll
    for (int o = 16; o; o >>= 1) s += __shfl_xor_sync(0xffffffffu, s, o);
    if (lane == 0) g_rowoff[row] = m + __logf(s);
}

// ---------------- TF32 agg v2: agg[b,p,:] = sum_{q<=p} exp(l[p,q]-off[p]) * x[b,q,:]
// block 64 rows x 256 cols, 8 warps (2m x 4n), warp tile 32x64.
// A (exp weights) [m=64][k=32] stride 36 via ldmatrix; B (x) [k=32][n=256] stride 264.
#define AG_AS 36
#define AG_BS 264

__global__ __launch_bounds__(256) void k_agg_tf32(const float* __restrict__ x)
{
    __shared__ float As[64 * AG_AS];   // 9216 B
    __shared__ float Bs[32 * AG_BS];   // 33792 B

    const uint32_t asb = (uint32_t)__cvta_generic_to_shared(As);
    const uint32_t bsb = (uint32_t)__cvta_generic_to_shared(Bs);
    const uint32_t* BsU = (const uint32_t*)Bs;

    const int b  = blockIdx.z;
    const int p0 = blockIdx.x * 64;
    const int tid  = threadIdx.x;
    const int lane = tid & 31;
    const int warp = tid >> 5;
    const int wm = (warp & 1) * 32;
    const int wn = (warp >> 1) * 64;
    const int g   = lane >> 2;
    const int tig = lane & 3;

    // exp-weight loader: thread handles row ar, 8 k's starting at ac8
    const int ar  = tid >> 2;              // 0..63
    const int ac8 = (tid & 3) * 8;
    const int prow = p0 + ar;
    const float off = g_rowoff[b * P_ + prow];
    const float* Lp = g_logits + (size_t)(b * P_ + prow) * P_ + ac8;

    const float* xb = x + (size_t)b * P_ * D_;

    const int rowit = (lane & 7) + ((lane & 8) ? 8 : 0);
    const int colw  = (lane & 16) ? 4 : 0;

    float4 acc[2][8];
#pragma unroll
    for (int mi = 0; mi < 2; mi++)
#pragma unroll
        for (int ni = 0; ni < 8; ni++) acc[mi][ni] = make_float4(0.f, 0.f, 0.f, 0.f);

    const int nkt = (p0 + 64) / 32;

    // preload logits regs for kt=0
    float4 l0 = *(const float4*)(Lp + 0);
    float4 l1 = *(const float4*)(Lp + 4);

    for (int kt = 0; kt < nkt; kt++) {
        const int k0 = kt * 32;
        __syncthreads();   // previous tile fully consumed

        // exp + mask + store A tile
        {
            int kq = k0 + ac8;
            float4 e0, e1;
            e0.x = (kq     <= prow) ? __expf(l0.x - off) : 0.f;
            e0.y = (kq + 1 <= prow) ? __expf(l0.y - off) : 0.f;
            e0.z = (kq + 2 <= prow) ? __expf(l0.z - off) : 0.f;
            e0.w = (kq + 3 <= prow) ? __expf(l0.w - off) : 0.f;
            e1.x = (kq + 4 <= prow) ? __expf(l1.x - off) : 0.f;
            e1.y = (kq + 5 <= prow) ? __expf(l1.y - off) : 0.f;
            e1.z = (kq + 6 <= prow) ? __expf(l1.z - off) : 0.f;
            e1.w = (kq + 7 <= prow) ? __expf(l1.w - off) : 0.f;
            *(float4*)&As[ar * AG_AS + ac8]     = e0;
            *(float4*)&As[ar * AG_AS + ac8 + 4] = e1;
        }

        // cp.async x tile [k=32][n=256]
#pragma unroll
        for (int t = 0; t < 8; t++) {
            int id = tid + t * 256;
            int krow = id >> 6;
            int n4 = (id & 63) * 4;
            cp16(bsb + (uint32_t)(krow * AG_BS + n4) * 4,
                 xb + (size_t)(k0 + krow) * D_ + n4);
        }
        CP_COMMIT();

        // preload next logits regs (overlaps cp.async)
        if (kt + 1 < nkt) {
            l0 = *(const float4*)(Lp + k0 + 32);
            l1 = *(const float4*)(Lp + k0 + 36);
        }

        CP_WAIT(0);
        __syncthreads();

        const uint32_t aBase = asb + (uint32_t)((wm + rowit) * AG_AS + colw) * 4;
#pragma unroll
        for (int ks = 0; ks < 4; ks++) {
            uint32_t af[2][4];
#pragma unroll
            for (int mi = 0; mi < 2; mi++)
                ldsm_x4(af[mi], aBase + (uint32_t)(mi * 16 * AG_AS * 4 + ks * 32));
            uint32_t bf[8][2];
#pragma unroll
            for (int ni = 0; ni < 8; ni++) {
                int c = wn + ni * 8 + g;
                bf[ni][0] = BsU[(ks * 8 + tig) * AG_BS + c];
                bf[ni][1] = BsU[(ks * 8 + tig + 4) * AG_BS + c];
            }
#pragma unroll
            for (int mi = 0; mi < 2; mi++)
#pragma unroll
                for (int ni = 0; ni < 8; ni++)
                    mma_tf32(acc[mi][ni], af[mi], bf[ni]);
        }
    }

#pragma unroll
    for (int mi = 0; mi < 2; mi++) {
        int r = p0 + wm + mi * 16 + g;
#pragma unroll
        for (int ni = 0; ni < 8; ni++) {
            int c = wn + ni * 8 + tig * 2;
            float2 v0 = make_float2(acc[mi][ni].x, acc[mi][ni].y);
            float2 v1 = make_float2(acc[mi][ni].z, acc[mi][ni].w);
            *(float2*)(g_agg + (size_t)(b * P_ + r) * D_ + c) = v0;
            *(float2*)(g_agg + (size_t)(b * P_ + r + 8) * D_ + c) = v1;
        }
    }
}

// ---------------- kernel: out = LN(agg@mlp_w + mlp_b + wc*x) * ln_g + ln_b
__global__ __launch_bounds__(256) void k_final(
    const float* __restrict__ x, const float* __restrict__ mlp_w,
    const float* __restrict__ mlp_b, const float* __restrict__ ln_g,
    const float* __restrict__ ln_b, float* __restrict__ out)
{
    const int row0 = blockIdx.x * 32;
    const int tid = threadIdx.x;
    const int tx  = tid & 31;
    const int ty  = tid >> 5;

    __shared__ float As[16][36];
    __shared__ float Bs[16][256];
    __shared__ float s_mb[256], s_g[256], s_b[256];

    s_mb[tid] = mlp_b[tid];
    s_g[tid]  = ln_g[tid];
    s_b[tid]  = ln_b[tid];

    const int ar = tid >> 3;
    const int ac = (tid & 7) * 2;
    const float* Ap = g_agg + (size_t)(row0 + ar) * D_ + ac;

    float acc[4][8];
#pragma unroll
    for (int i = 0; i < 4; i++)
#pragma unroll
        for (int j = 0; j < 8; j++) acc[i][j] = 0.f;

    __syncthreads();
    for (int k0 = 0; k0 < D_; k0 += 16) {
        float2 a2 = *(const float2*)(Ap + k0);
        float4 bv[4];
#pragma unroll
        for (int t = 0; t < 4; t++) {
            int idx4 = tid + t * 256;
            int br = idx4 >> 6;
            int bc = (idx4 & 63) * 4;
            bv[t] = *(const float4*)(mlp_w + (size_t)(k0 + br) * D_ + bc);
        }
        As[ac][ar] = a2.x;
        As[ac + 1][ar] = a2.y;
#pragma unroll
        for (int t = 0; t < 4; t++) {
            int idx4 = tid + t * 256;
            int br = idx4 >> 6;
            int bc = (idx4 & 63) * 4;
            *(float4*)&Bs[br][bc] = bv[t];
        }
        __syncthreads();
#pragma unroll
        for (int k = 0; k < 16; k++) {
            float4 a  = *(const float4*)&As[k][ty * 4];
            float4 b0 = *(const float4*)&Bs[k][tx * 4];
            float4 b1 = *(const float4*)&Bs[k][tx * 4 + 128];
            float av[4] = {a.x, a.y, a.z, a.w};
            float bb[8] = {b0.x, b0.y, b0.z, b0.w, b1.x, b1.y, b1.z, b1.w};
#pragma unroll
            for (int i = 0; i < 4; i++)
#pragma unroll
                for (int j = 0; j < 8; j++)
                    acc[i][j] += av[i] * bb[j];
        }
        __syncthreads();
    }

#pragma unroll
    for (int i = 0; i < 4; i++) {
        int r = row0 + ty * 4 + i;
        float w = g_wc[r];
        const float* xr = x + (size_t)r * D_;
        float4 x0 = *(const float4*)(xr + tx * 4);
        float4 x1 = *(const float4*)(xr + tx * 4 + 128);
        float xv[8] = {x0.x, x0.y, x0.z, x0.w, x1.x, x1.y, x1.z, x1.w};
        float h[8];
#pragma unroll
        for (int j = 0; j < 8; j++) {
            int c = (j < 4) ? (tx * 4 + j) : (tx * 4 + 128 + (j - 4));
            h[j] = acc[i][j] + s_mb[c] + w * xv[j];
        }
        float s = 0.f;
#pragma unroll
        for (int j = 0; j < 8; j++) s += h[j];
#pragma unroll
        for (int o = 16; o; o >>= 1) s += __shfl_xor_sync(0xffffffffu, s, o);
        float mu = s * (1.0f / 256.0f);
        float d = 0.f;
#pragma unroll
        for (int j = 0; j < 8; j++) { float t = h[j] - mu; d += t * t; }
#pragma unroll
        for (int o = 16; o; o >>= 1) d += __shfl_xor_sync(0xffffffffu, d, o);
        float inv = rsqrtf(d * (1.0f / 256.0f) + 1e-5f);

        float y[8];
#pragma unroll
        for (int j = 0; j < 8; j++) {
            int c = (j < 4) ? (tx * 4 + j) : (tx * 4 + 128 + (j - 4));
            y[j] = (h[j] - mu) * inv * s_g[c] + s_b[c];
        }
        float4 w0 = make_float4(y[0], y[1], y[2], y[3]);
        float4 w1 = make_float4(y[4], y[5], y[6], y[7]);
        *(float4*)(out + (size_t)r * D_ + tx * 4) = w0;
        *(float4*)(out + (size_t)r * D_ + tx * 4 + 128) = w1;
    }
}

// ---------------- launch ----------------
extern "C" void kernel_launch(void* const* d_in, const int* in_sizes, int n_in,
                              void* d_out, int out_size)
{
    const float* x      = (const float*)d_in[0];
    const float* mlp_w  = (const float*)d_in[1];
    const float* mlp_b  = (const float*)d_in[2];
    const float* his_w  = (const float*)d_in[3];
    const float* his_b  = (const float*)d_in[4];
    const float* cur_w  = (const float*)d_in[5];
    const float* cur_b  = (const float*)d_in[6];
    const float* wl_w   = (const float*)d_in[7];
    const float* wl_b   = (const float*)d_in[8];
    const float* gate_w = (const float*)d_in[9];
    const float* gate_b = (const float*)d_in[10];
    const float* ln_g   = (const float*)d_in[11];
    const float* ln_b   = (const float*)d_in[12];
    float* out = (float*)d_out;

    void* pH = nullptr;
    void* pL = nullptr;
    cudaGetSymbolAddress(&pH, g_H);
    cudaGetSymbolAddress(&pL, g_logits);
    float* gH = (float*)pH;
    float* gL = (float*)pL;

    const int gemm_smem = (G_STG * 2) * 4;   // 71680 bytes
    cudaFuncSetAttribute(k_gemm_tf32, cudaFuncAttributeMaxDynamicSharedMemorySize, gemm_smem);

    // 1) fused gate weight precompute
    k_weff<<<1, 256>>>(cur_w, cur_b, gate_w, gate_b);
    // 2) per-row gate scalar wc
    k_wc<<<BP_ / 8, 256>>>(x);
    // 3) H = x @ his_w + his_b   (tf32, ldmatrix + cp.async)
    k_gemm_tf32<<<dim3(D_ / 128, BP_ / 128), 256, gemm_smem>>>(x, his_w, his_b, gH, D_, D_);
    // 4) logits = H @ wl_w + wl_b
    k_gemm_tf32<<<dim3(P_ / 128, BP_ / 128), 256, gemm_smem>>>(gH, wl_w, wl_b, gL, P_, D_);
    // 5) per-row softmax offsets
    k_rowstat<<<BP_ / 8, 256>>>();
    // 6) agg = tril(softmax(logits)) @ x  (tf32, 64-row blocks, triangular skip)
    k_agg_tf32<<<dim3(P_ / 64, 1, B_), 256>>>(x);
    // 7) out = LN(agg @ mlp_w + mlp_b + wc*x)
    k_final<<<BP_ / 32, 256>>>(x, mlp_w, mlp_b, ln_g, ln_b, out);
    // 8) second output: origin (copy of x)
    cudaMemcpyAsync(out + (size_t)BP_ * D_, x,
                    (size_t)BP_ * D_ * sizeof(float),
                    cudaMemcpyDeviceToDevice);
}

// round 8
// speedup vs baseline: 2.3626x; 1.1055x over previous
#include <cuda_runtime.h>
#include <cstdint>
#include <cstddef>

#define B_  32
#define P_  2048
#define D_  256
#define BP_ (B_ * P_)   // 65536

// ---------------- device scratch ----------------
__device__ float g_H[(size_t)BP_ * D_];        // 64 MB
__device__ float g_logits[(size_t)BP_ * P_];   // 512 MB
__device__ float g_agg[(size_t)BP_ * D_];      // 64 MB
__device__ float g_rowoff[BP_];                // m + log(sum exp)
__device__ float g_wc[BP_];                    // per-row gate scalar
__device__ float g_weff[D_];
__device__ float g_beff;

// ---------------- helpers ----------------
__device__ __forceinline__ void mma_tf32(float4& c, const uint32_t a[4], const uint32_t b[2]) {
    asm volatile(
        "mma.sync.aligned.m16n8k8.row.col.f32.tf32.tf32.f32 "
        "{%0,%1,%2,%3}, {%4,%5,%6,%7}, {%8,%9}, {%0,%1,%2,%3};\n"
        : "+f"(c.x), "+f"(c.y), "+f"(c.z), "+f"(c.w)
        : "r"(a[0]), "r"(a[1]), "r"(a[2]), "r"(a[3]),
          "r"(b[0]), "r"(b[1]));
}

__device__ __forceinline__ void ldsm_x4(uint32_t r[4], uint32_t addr) {
    asm volatile("ldmatrix.sync.aligned.m8n8.x4.shared.b16 {%0,%1,%2,%3}, [%4];"
                 : "=r"(r[0]), "=r"(r[1]), "=r"(r[2]), "=r"(r[3]) : "r"(addr));
}

__device__ __forceinline__ void cp16(uint32_t dst_smem, const void* src) {
    asm volatile("cp.async.cg.shared.global [%0], [%1], 16;\n"
                 :: "r"(dst_smem), "l"(src));
}
#define CP_COMMIT()  asm volatile("cp.async.commit_group;\n" ::: "memory")
#define CP_WAIT(n)   asm volatile("cp.async.wait_group %0;\n" :: "n"(n) : "memory")

// ---------------- kernel: w_eff = cur_w @ gate_w, b_eff = cur_b.gate_w + gate_b
__global__ void k_weff(const float* __restrict__ cur_w, const float* __restrict__ cur_b,
                       const float* __restrict__ gate_w, const float* __restrict__ gate_b)
{
    __shared__ float gw[D_];
    __shared__ float red[D_];
    int k = threadIdx.x;
    gw[k] = gate_w[k];
    __syncthreads();
    float s = 0.f;
#pragma unroll 8
    for (int d = 0; d < D_; d++) s += cur_w[k * D_ + d] * gw[d];
    g_weff[k] = s;
    red[k] = cur_b[k] * gw[k];
    __syncthreads();
    for (int off = 128; off > 0; off >>= 1) {
        if (k < off) red[k] += red[k + off];
        __syncthreads();
    }
    if (k == 0) g_beff = red[0] + gate_b[0];
}

// ---------------- kernel: wc[row] = x[row,:].w_eff + b_eff  (1 warp / row)
__global__ void k_wc(const float* __restrict__ x)
{
    int row  = blockIdx.x * 8 + (threadIdx.x >> 5);
    int lane = threadIdx.x & 31;
    const float* xr = x + (size_t)row * D_;
    float s = 0.f;
#pragma unroll
    for (int i = 0; i < 8; i++) s += xr[lane + 32 * i] * g_weff[lane + 32 * i];
#pragma unroll
    for (int o = 16; o; o >>= 1) s += __shfl_xor_sync(0xffffffffu, s, o);
    if (lane == 0) g_wc[row] = s + g_beff;
}

// ---------------- TF32 GEMM: C[M,N] = A[M,K]@B[K,N] + bias[N]
// block 128x128, 8 warps (2m x 4n), warp tile 64x32, K-step 32.
// A smem [m][k] stride 36 (ldmatrix.x4); B smem [k][n] stride 136 (pad-8).
// Double-buffered cp.async. __launch_bounds__(256,2): 128-reg cap -> 2 CTAs/SM.
#define G_AS 36
#define G_BS 136
#define G_AW (128 * G_AS)            // 4608 words
#define G_BW (32 * G_BS)             // 4352 words
#define G_STG (G_AW + G_BW)          // 8960 words per stage

__global__ __launch_bounds__(256, 2) void k_gemm_tf32(
    const float* __restrict__ A, const float* __restrict__ Bm,
    const float* __restrict__ bias, float* __restrict__ C,
    int N, int K)
{
    extern __shared__ float sm[];
    const uint32_t smb = (uint32_t)__cvta_generic_to_shared(sm);
    const uint32_t* smu = (const uint32_t*)sm;

    const int tid  = threadIdx.x;
    const int lane = tid & 31;
    const int warp = tid >> 5;
    const int wm = (warp & 1) * 64;
    const int wn = (warp >> 1) * 32;
    const int g   = lane >> 2;
    const int tig = lane & 3;
    const int row0 = blockIdx.y * 128;
    const int col0 = blockIdx.x * 128;

    // loaders
    const int am = tid & 127;
    const int aq = (tid >> 7) * 16;
    const float* Ap = A + (size_t)(row0 + am) * K + aq;
    const int bk  = tid >> 5;           // 0..7
    const int bn4 = (tid & 31) * 4;
    const float* Bp = Bm + (size_t)bk * N + col0 + bn4;

    // ldmatrix lane pointer components
    const int rowit = (lane & 7) + ((lane & 8) ? 8 : 0);
    const int colw  = (lane & 16) ? 4 : 0;

    float4 acc[4][4];
#pragma unroll
    for (int mi = 0; mi < 4; mi++)
#pragma unroll
        for (int ni = 0; ni < 4; ni++) acc[mi][ni] = make_float4(0.f, 0.f, 0.f, 0.f);

    const int nk = K / 32;

    // stage 0 loads
    {
        uint32_t base = smb;
#pragma unroll
        for (int v = 0; v < 4; v++)
            cp16(base + (uint32_t)(am * G_AS + aq + v * 4) * 4, Ap + v * 4);
#pragma unroll
        for (int v = 0; v < 4; v++)
            cp16(base + (uint32_t)(G_AW + (bk + v * 8) * G_BS + bn4) * 4,
                 Bp + (size_t)(v * 8) * N);
        CP_COMMIT();
    }

    for (int kt = 0; kt < nk; kt++) {
        const int s = kt & 1;
        if (kt + 1 < nk) {
            uint32_t base = smb + (uint32_t)((s ^ 1) * G_STG) * 4;
            const int k0 = (kt + 1) * 32;
#pragma unroll
            for (int v = 0; v < 4; v++)
                cp16(base + (uint32_t)(am * G_AS + aq + v * 4) * 4, Ap + k0 + v * 4);
#pragma unroll
            for (int v = 0; v < 4; v++)
                cp16(base + (uint32_t)(G_AW + (bk + v * 8) * G_BS + bn4) * 4,
                     Bp + (size_t)(k0 + v * 8) * N);
            CP_COMMIT();
            CP_WAIT(1);
        } else {
            CP_WAIT(0);
        }
        __syncthreads();

        const uint32_t aBase = smb + (uint32_t)(s * G_STG + (wm + rowit) * G_AS + colw) * 4;
        const int bBase = s * G_STG + G_AW;
#pragma unroll
        for (int ks = 0; ks < 4; ks++) {
            uint32_t af[4][4];
#pragma unroll
            for (int mi = 0; mi < 4; mi++)
                ldsm_x4(af[mi], aBase + (uint32_t)(mi * 16 * G_AS * 4 + ks * 32));
            uint32_t bf[4][2];
#pragma unroll
            for (int ni = 0; ni < 4; ni++) {
                int c = wn + ni * 8 + g;
                bf[ni][0] = smu[bBase + (ks * 8 + tig) * G_BS + c];
                bf[ni][1] = smu[bBase + (ks * 8 + tig + 4) * G_BS + c];
            }
#pragma unroll
            for (int mi = 0; mi < 4; mi++)
#pragma unroll
                for (int ni = 0; ni < 4; ni++)
                    mma_tf32(acc[mi][ni], af[mi], bf[ni]);
        }
        __syncthreads();
    }

    // epilogue: +bias, store
#pragma unroll
    for (int mi = 0; mi < 4; mi++) {
        int r = row0 + wm + mi * 16 + g;
#pragma unroll
        for (int ni = 0; ni < 4; ni++) {
            int c = col0 + wn + ni * 8 + tig * 2;
            float b0 = bias[c], b1 = bias[c + 1];
            float2 v0 = make_float2(acc[mi][ni].x + b0, acc[mi][ni].y + b1);
            float2 v1 = make_float2(acc[mi][ni].z + b0, acc[mi][ni].w + b1);
            *(float2*)(C + (size_t)r * N + c) = v0;
            *(float2*)(C + (size_t)(r + 8) * N + c) = v1;
        }
    }
}

// ---------------- per-row softmax offset = max + log(sum exp)  (1 warp / row)
__global__ void k_rowstat()
{
    int row  = blockIdx.x * 8 + (threadIdx.x >> 5);
    int lane = threadIdx.x & 31;
    const float4* L4 = (const float4*)(g_logits + (size_t)row * P_);
    float m = -1e30f;
#pragma unroll 4
    for (int i = lane; i < P_ / 4; i += 32) {
        float4 v = L4[i];
        m = fmaxf(m, fmaxf(fmaxf(v.x, v.y), fmaxf(v.z, v.w)));
    }
#pragma unroll
    for (int o = 16; o; o >>= 1) m = fmaxf(m, __shfl_xor_sync(0xffffffffu, m, o));
    float s = 0.f;
#pragma unroll 4
    for (int i = lane; i < P_ / 4; i += 32) {
        float4 v = L4[i];
        s += __expf(v.x - m) + __expf(v.y - m) + __expf(v.z - m) + __expf(v.w - m);
    }
#pragma unroll
    for (int o = 16; o; o >>= 1) s += __shfl_xor_sync(0xffffffffu, s, o);
    if (lane == 0) g_rowoff[row] = m + __logf(s);
}

// ---------------- TF32 agg: agg[b,p,:] = sum_{q<=p} exp(l[p,q]-off[p]) * x[b,q,:]
// block 64 rows x 256 cols, 8 warps (2m x 4n), warp tile 32x64.
#define AG_AS 36
#define AG_BS 264

__global__ __launch_bounds__(256, 2) void k_agg_tf32(const float* __restrict__ x)
{
    __shared__ float As[64 * AG_AS];   // 9216 B
    __shared__ float Bs[32 * AG_BS];   // 33792 B

    const uint32_t asb = (uint32_t)__cvta_generic_to_shared(As);
    const uint32_t bsb = (uint32_t)__cvta_generic_to_shared(Bs);
    const uint32_t* BsU = (const uint32_t*)Bs;

    const int b  = blockIdx.z;
    const int p0 = blockIdx.x * 64;
    const int tid  = threadIdx.x;
    const int lane = tid & 31;
    const int warp = tid >> 5;
    const int wm = (warp & 1) * 32;
    const int wn = (warp >> 1) * 64;
    const int g   = lane >> 2;
    const int tig = lane & 3;

    // exp-weight loader: thread handles row ar, 8 k's starting at ac8
    const int ar  = tid >> 2;              // 0..63
    const int ac8 = (tid & 3) * 8;
    const int prow = p0 + ar;
    const float off = g_rowoff[b * P_ + prow];
    const float* Lp = g_logits + (size_t)(b * P_ + prow) * P_ + ac8;

    const float* xb = x + (size_t)b * P_ * D_;

    const int rowit = (lane & 7) + ((lane & 8) ? 8 : 0);
    const int colw  = (lane & 16) ? 4 : 0;

    float4 acc[2][8];
#pragma unroll
    for (int mi = 0; mi < 2; mi++)
#pragma unroll
        for (int ni = 0; ni < 8; ni++) acc[mi][ni] = make_float4(0.f, 0.f, 0.f, 0.f);

    const int nkt = (p0 + 64) / 32;

    // preload logits regs for kt=0
    float4 l0 = *(const float4*)(Lp + 0);
    float4 l1 = *(const float4*)(Lp + 4);

    for (int kt = 0; kt < nkt; kt++) {
        const int k0 = kt * 32;
        __syncthreads();   // previous tile fully consumed

        // exp + mask + store A tile
        {
            int kq = k0 + ac8;
            float4 e0, e1;
            e0.x = (kq     <= prow) ? __expf(l0.x - off) : 0.f;
            e0.y = (kq + 1 <= prow) ? __expf(l0.y - off) : 0.f;
            e0.z = (kq + 2 <= prow) ? __expf(l0.z - off) : 0.f;
            e0.w = (kq + 3 <= prow) ? __expf(l0.w - off) : 0.f;
            e1.x = (kq + 4 <= prow) ? __expf(l1.x - off) : 0.f;
            e1.y = (kq + 5 <= prow) ? __expf(l1.y - off) : 0.f;
            e1.z = (kq + 6 <= prow) ? __expf(l1.z - off) : 0.f;
            e1.w = (kq + 7 <= prow) ? __expf(l1.w - off) : 0.f;
            *(float4*)&As[ar * AG_AS + ac8]     = e0;
            *(float4*)&As[ar * AG_AS + ac8 + 4] = e1;
        }

        // cp.async x tile [k=32][n=256]
#pragma unroll
        for (int t = 0; t < 8; t++) {
            int id = tid + t * 256;
            int krow = id >> 6;
            int n4 = (id & 63) * 4;
            cp16(bsb + (uint32_t)(krow * AG_BS + n4) * 4,
                 xb + (size_t)(k0 + krow) * D_ + n4);
        }
        CP_COMMIT();

        // preload next logits regs (overlaps cp.async)
        if (kt + 1 < nkt) {
            l0 = *(const float4*)(Lp + k0 + 32);
            l1 = *(const float4*)(Lp + k0 + 36);
        }

        CP_WAIT(0);
        __syncthreads();

        const uint32_t aBase = asb + (uint32_t)((wm + rowit) * AG_AS + colw) * 4;
#pragma unroll
        for (int ks = 0; ks < 4; ks++) {
            uint32_t af[2][4];
#pragma unroll
            for (int mi = 0; mi < 2; mi++)
                ldsm_x4(af[mi], aBase + (uint32_t)(mi * 16 * AG_AS * 4 + ks * 32));
            uint32_t bf[8][2];
#pragma unroll
            for (int ni = 0; ni < 8; ni++) {
                int c = wn + ni * 8 + g;
                bf[ni][0] = BsU[(ks * 8 + tig) * AG_BS + c];
                bf[ni][1] = BsU[(ks * 8 + tig + 4) * AG_BS + c];
            }
#pragma unroll
            for (int mi = 0; mi < 2; mi++)
#pragma unroll
                for (int ni = 0; ni < 8; ni++)
                    mma_tf32(acc[mi][ni], af[mi], bf[ni]);
        }
    }

#pragma unroll
    for (int mi = 0; mi < 2; mi++) {
        int r = p0 + wm + mi * 16 + g;
#pragma unroll
        for (int ni = 0; ni < 8; ni++) {
            int c = wn + ni * 8 + tig * 2;
            float2 v0 = make_float2(acc[mi][ni].x, acc[mi][ni].y);
            float2 v1 = make_float2(acc[mi][ni].z, acc[mi][ni].w);
            *(float2*)(g_agg + (size_t)(b * P_ + r) * D_ + c) = v0;
            *(float2*)(g_agg + (size_t)(b * P_ + r + 8) * D_ + c) = v1;
        }
    }
}

// ---------------- kernel: out = LN(agg@mlp_w + mlp_b + wc*x) * ln_g + ln_b
__global__ __launch_bounds__(256) void k_final(
    const float* __restrict__ x, const float* __restrict__ mlp_w,
    const float* __restrict__ mlp_b, const float* __restrict__ ln_g,
    const float* __restrict__ ln_b, float* __restrict__ out)
{
    const int row0 = blockIdx.x * 32;
    const int tid = threadIdx.x;
    const int tx  = tid & 31;
    const int ty  = tid >> 5;

    __shared__ float As[16][36];
    __shared__ float Bs[16][256];
    __shared__ float s_mb[256], s_g[256], s_b[256];

    s_mb[tid] = mlp_b[tid];
    s_g[tid]  = ln_g[tid];
    s_b[tid]  = ln_b[tid];

    const int ar = tid >> 3;
    const int ac = (tid & 7) * 2;
    const float* Ap = g_agg + (size_t)(row0 + ar) * D_ + ac;

    float acc[4][8];
#pragma unroll
    for (int i = 0; i < 4; i++)
#pragma unroll
        for (int j = 0; j < 8; j++) acc[i][j] = 0.f;

    __syncthreads();
    for (int k0 = 0; k0 < D_; k0 += 16) {
        float2 a2 = *(const float2*)(Ap + k0);
        float4 bv[4];
#pragma unroll
        for (int t = 0; t < 4; t++) {
            int idx4 = tid + t * 256;
            int br = idx4 >> 6;
            int bc = (idx4 & 63) * 4;
            bv[t] = *(const float4*)(mlp_w + (size_t)(k0 + br) * D_ + bc);
        }
        As[ac][ar] = a2.x;
        As[ac + 1][ar] = a2.y;
#pragma unroll
        for (int t = 0; t < 4; t++) {
            int idx4 = tid + t * 256;
            int br = idx4 >> 6;
            int bc = (idx4 & 63) * 4;
            *(float4*)&Bs[br][bc] = bv[t];
        }
        __syncthreads();
#pragma unroll
        for (int k = 0; k < 16; k++) {
            float4 a  = *(const float4*)&As[k][ty * 4];
            float4 b0 = *(const float4*)&Bs[k][tx * 4];
            float4 b1 = *(const float4*)&Bs[k][tx * 4 + 128];
            float av[4] = {a.x, a.y, a.z, a.w};
            float bb[8] = {b0.x, b0.y, b0.z, b0.w, b1.x, b1.y, b1.z, b1.w};
#pragma unroll
            for (int i = 0; i < 4; i++)
#pragma unroll
                for (int j = 0; j < 8; j++)
                    acc[i][j] += av[i] * bb[j];
        }
        __syncthreads();
    }

#pragma unroll
    for (int i = 0; i < 4; i++) {
        int r = row0 + ty * 4 + i;
        float w = g_wc[r];
        const float* xr = x + (size_t)r * D_;
        float4 x0 = *(const float4*)(xr + tx * 4);
        float4 x1 = *(const float4*)(xr + tx * 4 + 128);
        float xv[8] = {x0.x, x0.y, x0.z, x0.w, x1.x, x1.y, x1.z, x1.w};
        float h[8];
#pragma unroll
        for (int j = 0; j < 8; j++) {
            int c = (j < 4) ? (tx * 4 + j) : (tx * 4 + 128 + (j - 4));
            h[j] = acc[i][j] + s_mb[c] + w * xv[j];
        }
        float s = 0.f;
#pragma unroll
        for (int j = 0; j < 8; j++) s += h[j];
#pragma unroll
        for (int o = 16; o; o >>= 1) s += __shfl_xor_sync(0xffffffffu, s, o);
        float mu = s * (1.0f / 256.0f);
        float d = 0.f;
#pragma unroll
        for (int j = 0; j < 8; j++) { float t = h[j] - mu; d += t * t; }
#pragma unroll
        for (int o = 16; o; o >>= 1) d += __shfl_xor_sync(0xffffffffu, d, o);
        float inv = rsqrtf(d * (1.0f / 256.0f) + 1e-5f);

        float y[8];
#pragma unroll
        for (int j = 0; j < 8; j++) {
            int c = (j < 4) ? (tx * 4 + j) : (tx * 4 + 128 + (j - 4));
            y[j] = (h[j] - mu) * inv * s_g[c] + s_b[c];
        }
        float4 w0 = make_float4(y[0], y[1], y[2], y[3]);
        float4 w1 = make_float4(y[4], y[5], y[6], y[7]);
        *(float4*)(out + (size_t)r * D_ + tx * 4) = w0;
        *(float4*)(out + (size_t)r * D_ + tx * 4 + 128) = w1;
    }
}

// ---------------- launch ----------------
extern "C" void kernel_launch(void* const* d_in, const int* in_sizes, int n_in,
                              void* d_out, int out_size)
{
    const float* x      = (const float*)d_in[0];
    const float* mlp_w  = (const float*)d_in[1];
    const float* mlp_b  = (const float*)d_in[2];
    const float* his_w  = (const float*)d_in[3];
    const float* his_b  = (const float*)d_in[4];
    const float* cur_w  = (const float*)d_in[5];
    const float* cur_b  = (const float*)d_in[6];
    const float* wl_w   = (const float*)d_in[7];
    const float* wl_b   = (const float*)d_in[8];
    const float* gate_w = (const float*)d_in[9];
    const float* gate_b = (const float*)d_in[10];
    const float* ln_g   = (const float*)d_in[11];
    const float* ln_b   = (const float*)d_in[12];
    float* out = (float*)d_out;

    void* pH = nullptr;
    void* pL = nullptr;
    cudaGetSymbolAddress(&pH, g_H);
    cudaGetSymbolAddress(&pL, g_logits);
    float* gH = (float*)pH;
    float* gL = (float*)pL;

    const int gemm_smem = (G_STG * 2) * 4;   // 71680 bytes
    cudaFuncSetAttribute(k_gemm_tf32, cudaFuncAttributeMaxDynamicSharedMemorySize, gemm_smem);

    // 1) fused gate weight precompute
    k_weff<<<1, 256>>>(cur_w, cur_b, gate_w, gate_b);
    // 2) per-row gate scalar wc
    k_wc<<<BP_ / 8, 256>>>(x);
    // 3) H = x @ his_w + his_b
    k_gemm_tf32<<<dim3(D_ / 128, BP_ / 128), 256, gemm_smem>>>(x, his_w, his_b, gH, D_, D_);
    // 4) logits = H @ wl_w + wl_b
    k_gemm_tf32<<<dim3(P_ / 128, BP_ / 128), 256, gemm_smem>>>(gH, wl_w, wl_b, gL, P_, D_);
    // 5) per-row softmax offsets
    k_rowstat<<<BP_ / 8, 256>>>();
    // 6) agg = tril(softmax(logits)) @ x
    k_agg_tf32<<<dim3(P_ / 64, 1, B_), 256>>>(x);
    // 7) out = LN(agg @ mlp_w + mlp_b + wc*x)
    k_final<<<BP_ / 32, 256>>>(x, mlp_w, mlp_b, ln_g, ln_b, out);
    // 8) second output: origin (copy of x)
    cudaMemcpyAsync(out + (size_t)BP_ * D_, x,
                    (size_t)BP_ * D_ * sizeof(float),
                    cudaMemcpyDeviceToDevice);
}